// round 11
// baseline (speedup 1.0000x reference)
#include <cuda_runtime.h>
#include <cstdint>

#define SEQ 4096
#define HID 256
#define EMB 256

// ---------------------------------------------------------------------------
// Scratch: x_proj[t][j] (4096 x 256 fp32 = 4 MB). Device global (no alloc).
// ---------------------------------------------------------------------------
__device__ float g_xproj[SEQ * HID];

// ---------------------------------------------------------------------------
// Phase 1: x_proj = embedding[tokens] @ wx_w.T + wx_b  (~25us)
// ---------------------------------------------------------------------------
#define TOK_PER_BLK 16

__global__ __launch_bounds__(256) void xproj_kernel(
    const int* __restrict__ tokens,
    const float* __restrict__ embedding,
    const float* __restrict__ wx_w,
    const float* __restrict__ wx_b)
{
    __shared__ float emb_sm[TOK_PER_BLK * EMB];
    const int tid = threadIdx.x;
    const int t0  = blockIdx.x * TOK_PER_BLK;

    #pragma unroll
    for (int i = 0; i < TOK_PER_BLK; i++) {
        long tok = (long)tokens[t0 + i];
        emb_sm[i * EMB + tid] = embedding[tok * (long)EMB + tid];
    }
    __syncthreads();

    float acc[TOK_PER_BLK];
    #pragma unroll
    for (int i = 0; i < TOK_PER_BLK; i++) acc[i] = 0.f;

    const float4* wrow = reinterpret_cast<const float4*>(wx_w + tid * EMB);
    #pragma unroll 4
    for (int k4 = 0; k4 < EMB / 4; k4++) {
        float4 w = wrow[k4];
        #pragma unroll
        for (int i = 0; i < TOK_PER_BLK; i++) {
            float4 e = *reinterpret_cast<const float4*>(&emb_sm[i * EMB + 4 * k4]);
            acc[i] += w.x * e.x + w.y * e.y + w.z * e.z + w.w * e.w;
        }
    }

    const float b = wx_b[tid];
    #pragma unroll
    for (int i = 0; i < TOK_PER_BLK; i++)
        g_xproj[(t0 + i) * HID + tid] = acc[i] + b;
}

// ---------------------------------------------------------------------------
// Phase 2: serial recurrence, 8-CTA cluster, BARRIER-FREE loop.
//
// CTA r owns h slice [r*32, r*32+32); every dot it performs reads ONLY that
// slice, so h never crosses the cluster — only 1-float partials do.
//
// Epoch-tagged h (no __syncthreads in the loop):
//   owner warp stores hbuf[nxt][lane] = h + k', k' = ((t+1)&3)+1.
//   Every warp: lane L polls word L of hbuf[cur] until its uint is in
//   [float(k), float(k+1)] (h in [0,1] -> value in [k,k+1]; stale epochs
//   differ by 2 mod 4 -> disjoint ranges), __syncwarp, vector-load the slice,
//   dot, and cancel the tag with one FMA: s = dot - k*rowsum.
//
// Slot-reuse safety WITHOUT a bar (causal round-trip argument):
//   owner r's write of hbuf[cur(t)] happens at end of step t+1, which needs
//   its inbox row full at t+1; slot j is shipped by CTA j's warp r at t+1,
//   which required CTA j owner's step-t h, which consumed the partial that
//   CTA r's warp j shipped AFTER its step-t read of hbuf[cur(t)]. So every
//   local warp's step-t read precedes the overwrite, for all j. Inbox rows:
//   owner re-arms row[cur] at t (STS, program-ordered before its tagged-h
//   store); the next write into that row (any CTA's warp r at t+2) is >= 2
//   DSMEM flights later on the same causal chain.
//
// Roles (o = tid, 256 threads; owner CTA of o = o>>5 = warp id):
//   sender warp (7 of 8): dot -> one st.shared::cluster into owner's inbox.
//   owner warp (warp 'rank'): dot -> deposit (s + bias + x_proj folded in)
//   -> poll full 8-slot row (two volatile 16B loads) -> re-arm -> sum8 ->
//   sigmoid -> tagged store into hbuf[nxt].
// ---------------------------------------------------------------------------
#define NCTA 8
#define THREADS2 256
#define SLICE 32          // outputs (and k's) per CTA
#define SENTB 0xFFFFFFFFu
#define INBOX_WORDS 256   // 32 outputs x 8 sender slots (one buffer)

__device__ __forceinline__ uint32_t smem_u32(const void* p) {
    uint32_t a;
    asm("{ .reg .u64 t; cvta.to.shared.u64 t, %1; cvt.u32.u64 %0, t; }"
        : "=r"(a) : "l"(p));
    return a;
}
__device__ __forceinline__ uint32_t mapa_rank(uint32_t a, uint32_t rank) {
    uint32_t r;
    asm("mapa.shared::cluster.u32 %0, %1, %2;" : "=r"(r) : "r"(a), "r"(rank));
    return r;
}
__device__ __forceinline__ void st_remote_f32(uint32_t a, float v) {
    asm volatile("st.shared::cluster.f32 [%0], %1;" :: "r"(a), "f"(v) : "memory");
}
__device__ __forceinline__ void fma2(unsigned long long& acc,
                                     unsigned long long a, unsigned long long b) {
    asm("fma.rn.f32x2 %0, %1, %2, %0;" : "+l"(acc) : "l"(a), "l"(b));
}
__device__ __forceinline__ void add2(unsigned long long& d,
                                     unsigned long long a, unsigned long long b) {
    asm("add.rn.f32x2 %0, %1, %2;" : "=l"(d) : "l"(a), "l"(b));
}
__device__ __forceinline__ unsigned long long pack2(float x, float y) {
    unsigned long long v;
    asm("mov.b64 %0, {%1, %2};" : "=l"(v) : "f"(x), "f"(y));
    return v;
}
__device__ __forceinline__ void unpack2(unsigned long long v, float& x, float& y) {
    asm("mov.b64 {%0, %1}, %2;" : "=f"(x), "=f"(y) : "l"(v));
}
// volatile 16B smem load / store (for inbox row poll + re-arm)
__device__ __forceinline__ void ldsv4(uint32_t addr, unsigned& a, unsigned& b,
                                      unsigned& c, unsigned& d) {
    asm volatile("ld.volatile.shared.v4.u32 {%0,%1,%2,%3}, [%4];"
                 : "=r"(a), "=r"(b), "=r"(c), "=r"(d) : "r"(addr));
}
__device__ __forceinline__ void stsv4(uint32_t addr, unsigned a, unsigned b,
                                      unsigned c, unsigned d) {
    asm volatile("st.volatile.shared.v4.u32 [%0], {%1,%2,%3,%4};"
                 :: "r"(addr), "r"(a), "r"(b), "r"(c), "r"(d) : "memory");
}
__device__ __forceinline__ void stsv1(uint32_t addr, unsigned v) {
    asm volatile("st.volatile.shared.u32 [%0], %1;"
                 :: "r"(addr), "r"(v) : "memory");
}

__global__ __launch_bounds__(THREADS2, 1) __cluster_dims__(NCTA, 1, 1)
void rnn_kernel(const float* __restrict__ wh_w,
                const float* __restrict__ wh_b,
                float* __restrict__ out)
{
    __shared__ __align__(16) float    hbuf[2][SLICE];        // tagged own slice
    __shared__ __align__(16) unsigned inbox[2][INBOX_WORDS]; // [o&31][sender]

    const int tid = threadIdx.x;
    uint32_t rank; asm("mov.u32 %0, %%cluster_ctarank;" : "=r"(rank));

    const int o    = tid;            // GLOBAL output index 0..255
    const int lane = tid & 31;
    const int own  = o >> 5;         // owner CTA (= warp id) of output o
    const bool owner = (own == (int)rank);

    // Register-resident packed weights + rowsum (for tag cancellation)
    unsigned long long w[SLICE / 2];
    float rowsum = 0.f;
    {
        const float* row = wh_w + o * HID + (int)rank * SLICE;
        #pragma unroll
        for (int i = 0; i < SLICE / 2; i++) {
            float w0 = row[2 * i], w1 = row[2 * i + 1];
            w[i] = pack2(w0, w1);
            rowsum += w0 + w1;
        }
    }

    // Init: hbuf[0] = h0 + tag1 = 1.0 (h0=0); hbuf[1] = 0 (matches no tag).
    // Both inbox buffers armed with sentinel.
    if (tid < SLICE) { hbuf[0][tid] = 1.0f; hbuf[1][tid] = 0.0f; }
    reinterpret_cast<unsigned*>(inbox)[tid]            = SENTB;
    reinterpret_cast<unsigned*>(inbox)[tid + THREADS2] = SENTB;

    float bias = 0.f, xp_cur = 0.f, hn = 0.f;
    if (owner) {
        bias   = wh_b[o];
        xp_cur = g_xproj[o];
    }
    __syncthreads();
    // One-time: all CTAs' init visible before any remote store.
    asm volatile("barrier.cluster.arrive.aligned;" ::: "memory");
    asm volatile("barrier.cluster.wait.aligned;"   ::: "memory");

    // Sender: remote address of owner CTA's inbox slot [buf0][(o&31)*8 + rank]
    uint32_t dst = 0;
    if (!owner)
        dst = mapa_rank(smem_u32(&inbox[0][0]), (uint32_t)own)
            + (uint32_t)(((o & 31) << 3) + (int)rank) * 4u;
    // Owner: local base of its inbox row (32B, 16B-aligned)
    const uint32_t rowbase = smem_u32(&inbox[0][(o & 31) << 3]);
    const uint32_t BUFB = INBOX_WORDS * 4u;   // bytes between inbox buffers

    for (int t = 0; t < SEQ; t++) {
        const int   cur = t & 1;
        const int   nxt = cur ^ 1;
        const float kf  = (float)((t & 3) + 1);        // tag consumed this step
        const float kfn = (float)(((t + 1) & 3) + 1);  // tag we will store

        float xp_next = 0.f;
        if (owner && (t + 1 < SEQ))
            xp_next = __ldg(&g_xproj[(t + 1) * HID + o]);

        // ---- lane-poll for this epoch's tag on ONE hbuf word, then sync ----
        {
            const unsigned lo = __float_as_uint(kf);
            const unsigned hi = __float_as_uint(kf + 1.0f);
            volatile unsigned* ph =
                reinterpret_cast<volatile unsigned*>(&hbuf[cur][lane]);
            unsigned u = *ph;
            while (u < lo || u > hi) u = *ph;
        }
        __syncwarp();

        // ---- 32-MAC partial over tagged slice; 4 accumulator chains ----
        const ulonglong2* h2 =
            reinterpret_cast<const ulonglong2*>(&hbuf[cur][0]);
        unsigned long long a0 = 0ull, a1 = 0ull, a2 = 0ull, a3 = 0ull;
        #pragma unroll
        for (int i = 0; i < 8; i += 2) {
            ulonglong2 hva = h2[i];
            ulonglong2 hvb = h2[i + 1];
            fma2(a0, w[2 * i],     hva.x);
            fma2(a1, w[2 * i + 1], hva.y);
            fma2(a2, w[2 * i + 2], hvb.x);
            fma2(a3, w[2 * i + 3], hvb.y);
        }
        unsigned long long s01, s23, sp;
        add2(s01, a0, a1); add2(s23, a2, a3); add2(sp, s01, s23);
        float x0, y0;
        unpack2(sp, x0, y0);
        float s = fmaf(-kf, rowsum, x0 + y0);   // cancel tag*rowsum

        if (!owner) {
            // ship partial straight to the owner CTA
            st_remote_f32(dst + (uint32_t)cur * BUFB, s);
        } else {
            // deposit own partial WITH bias + x_proj folded in, then poll row
            const uint32_t rb = rowbase + (uint32_t)cur * BUFB;
            stsv1(rb + (uint32_t)rank * 4u, __float_as_uint(s + bias + xp_cur));
            unsigned v0, v1, v2, v3, v4, v5, v6, v7;
            for (;;) {
                ldsv4(rb,      v0, v1, v2, v3);
                ldsv4(rb + 16, v4, v5, v6, v7);
                if (v0 != SENTB && v1 != SENTB && v2 != SENTB && v3 != SENTB &&
                    v4 != SENTB && v5 != SENTB && v6 != SENTB && v7 != SENTB)
                    break;
            }
            // re-arm the row for step t+2 (program-ordered before hbuf store)
            stsv4(rb,      SENTB, SENTB, SENTB, SENTB);
            stsv4(rb + 16, SENTB, SENTB, SENTB, SENTB);

            float z = ((__uint_as_float(v0) + __uint_as_float(v1)) +
                       (__uint_as_float(v2) + __uint_as_float(v3))) +
                      ((__uint_as_float(v4) + __uint_as_float(v5)) +
                       (__uint_as_float(v6) + __uint_as_float(v7)));
            hn = __fdividef(1.f, 1.f + __expf(-z));
            hbuf[nxt][lane] = hn + kfn;        // tagged publish (no bar)
            xp_cur = xp_next;
        }
    }

    if (owner) out[o] = hn;
}

// ---------------------------------------------------------------------------
// kernel_launch
//   d_in: [0] tokens i32[4096], [1] embedding f32[128000*256],
//         [2] wx_w f32[256*256], [3] wx_b f32[256],
//         [4] wh_w f32[256*256], [5] wh_b f32[256]
// ---------------------------------------------------------------------------
extern "C" void kernel_launch(void* const* d_in, const int* in_sizes, int n_in,
                              void* d_out, int out_size)
{
    const int*   tokens    = (const int*)d_in[0];
    const float* embedding = (const float*)d_in[1];
    const float* wx_w      = (const float*)d_in[2];
    const float* wx_b      = (const float*)d_in[3];
    const float* wh_w      = (const float*)d_in[4];
    const float* wh_b      = (const float*)d_in[5];
    float*       out       = (float*)d_out;

    xproj_kernel<<<SEQ / TOK_PER_BLK, 256>>>(tokens, embedding, wx_w, wx_b);
    rnn_kernel<<<NCTA, THREADS2>>>(wh_w, wh_b, out);
}